// round 15
// baseline (speedup 1.0000x reference)
#include <cuda_runtime.h>

#define Bn   8
#define Hn   512
#define Wn   512
#define HWn  (Hn*Wn)        // 262144
#define NPIX (Bn*HWn)       // 2097152
#define NBC  24             // B*3 (b,c) pairs
#define NBINS 4096
#define RMAX 50
#define MAXWP (Wn + 2*RMAX) // 612
#define SEG  8              // rows per thread in vertical passes
#define NSEG (Hn/SEG)       // 64
#define HB_T 160            // hbox threads (160*4 = 640 >= MAXWP)
#define HB_ROWS 4           // rows per hbox4 block
#define VH_T 512            // fused vbox_ab+hbox2 threads
#define FIN_T 512           // vbox_fin threads per block

// ---------------- scratch (no allocation allowed: __device__ globals) -------
__device__ float g_h0[NPIX];
__device__ float g_h1[NPIX];
__device__ float g_h2[NPIX];   // reused as t_final after k_vh
__device__ float g_h3[NPIX];
__device__ unsigned int g_hist[NBC*NBINS];
__device__ float g_p[NBC*2];      // p_low, p_high per (b,c)

__device__ __forceinline__ int reflW(int j){ j = j < 0 ? -j : j; return j >= Wn ? 2*Wn - 2 - j : j; }
__device__ __forceinline__ int reflH(int j){ j = j < 0 ? -j : j; return j >= Hn ? 2*Hn - 2 - j : j; }
__device__ __forceinline__ int get_r(const int* rp){ int r = rp[0]; if (r < 1) r = 1; if (r > RMAX) r = RMAX; return r; }

__device__ __forceinline__ float4 f4add(float4 a, float4 b){ return make_float4(a.x+b.x,a.y+b.y,a.z+b.z,a.w+b.w); }
__device__ __forceinline__ float4 f4sub(float4 a, float4 b){ return make_float4(a.x-b.x,a.y-b.y,a.z-b.z,a.w-b.w); }
__device__ __forceinline__ float2 f2add(float2 a, float2 b){ return make_float2(a.x+b.x,a.y+b.y); }
__device__ __forceinline__ float2 f2sub(float2 a, float2 b){ return make_float2(a.x-b.x,a.y-b.y); }

// ---------------- warp shuffle scans ---------------------------------------
__device__ __forceinline__ float4 wscan4(float4 x, int lane)
{
    #pragma unroll
    for (int d = 1; d < 32; d <<= 1) {
        float a = __shfl_up_sync(0xFFFFFFFFu, x.x, d);
        float b = __shfl_up_sync(0xFFFFFFFFu, x.y, d);
        float c = __shfl_up_sync(0xFFFFFFFFu, x.z, d);
        float e = __shfl_up_sync(0xFFFFFFFFu, x.w, d);
        if (lane >= d) { x.x += a; x.y += b; x.z += c; x.w += e; }
    }
    return x;
}
__device__ __forceinline__ float2 wscan2(float2 x, int lane)
{
    #pragma unroll
    for (int d = 1; d < 32; d <<= 1) {
        float a = __shfl_up_sync(0xFFFFFFFFu, x.x, d);
        float b = __shfl_up_sync(0xFFFFFFFFu, x.y, d);
        if (lane >= d) { x.x += a; x.y += b; }
    }
    return x;
}
__device__ __forceinline__ unsigned int wscanu(unsigned int x, int lane)
{
    #pragma unroll
    for (int d = 1; d < 32; d <<= 1) {
        unsigned int a = __shfl_up_sync(0xFFFFFFFFu, x, d);
        if (lane >= d) x += a;
    }
    return x;
}

// ---------------- K1: 4-row staged gray/tg + horizontal box (+zero hist) ---
__global__ void k_hbox4(const int* __restrict__ rp,
                        const float* __restrict__ img,
                        const float* __restrict__ omega,
                        const float* __restrict__ atm)
{
    // piggyback: zero coarse histograms (1024 blocks * 96 = 98304 = 24*4096)
    if (threadIdx.x < 96) g_hist[blockIdx.x * 96 + threadIdx.x] = 0u;

    int r = get_r(rp);
    int Wp = Wn + 2*r;
    int grp = blockIdx.x;                 // 0..Bn*Hn/HB_ROWS-1
    int b = grp >> 7;                     // 128 groups per batch
    int y0 = (grp & 127) * HB_ROWS;
    const float* ib = img + (size_t)b * 3 * HWn;
    float om  = omega[b];
    float ra0 = 1.0f / (atm[b*3+0] + 1e-8f);
    float ra1 = 1.0f / (atm[b*3+1] + 1e-8f);
    float ra2 = 1.0f / (atm[b*3+2] + 1e-8f);
    int tid = threadIdx.x;
    int lane = tid & 31, wp = tid >> 5;

    __shared__ float4 P[MAXWP];
    __shared__ float4 wtot[HB_T/32];
    __shared__ float t0s[HB_ROWS+1][Wn];   // rows y0-1 .. y0+3 (clamped)
    __shared__ float sgray[HB_ROWS][Wn];
    __shared__ float stg[HB_ROWS][Wn];

    // stage rows y0..y0+3: gray + t0  (t0s[k+1] = row y0+k)
    for (int idx = tid; idx < HB_ROWS*Wn; idx += HB_T) {
        int k = idx >> 9, j = idx & 511;
        int pix = ((y0 + k) << 9) + j;
        float i0 = ib[pix], i1 = ib[HWn + pix], i2 = ib[2*HWn + pix];
        sgray[k][j] = 0.299f*i0 + 0.587f*i1 + 0.114f*i2;
        t0s[k+1][j] = 1.0f - om * fminf(i0*ra0, fminf(i1*ra1, i2*ra2));
    }
    // stage row y0-1 (clamped to 0) into t0s[0]
    {
        int yr = (y0 > 0) ? (y0 - 1) : 0;
        for (int j = tid; j < Wn; j += HB_T) {
            int pix = (yr << 9) + j;
            float i0 = ib[pix], i1 = ib[HWn + pix], i2 = ib[2*HWn + pix];
            t0s[0][j] = 1.0f - om * fminf(i0*ra0, fminf(i1*ra1, i2*ra2));
        }
    }
    __syncthreads();
    // tg rows: row y = y0+k uses t0s[k] (row y-1, clamped) and t0s[k+1] (row y)
    for (int idx = tid; idx < HB_ROWS*Wn; idx += HB_T) {
        int k = idx >> 9, j = idx & 511;
        int y = y0 + k;
        float t_yy_x = t0s[k][j];
        float txv;
        if (j == 0) txv = t_yy_x;
        else {
            float tm = t0s[k][j-1];
            txv = tm * __expf(-fabsf(t_yy_x - tm));
        }
        float tg;
        if (y == 0) tg = txv;
        else        tg = txv * __expf(-fabsf(t0s[k+1][j] - t_yy_x));
        stg[k][j] = tg;
    }
    __syncthreads();

    for (int k = 0; k < HB_ROWS; k++) {
        int y = y0 + k;
        int base = (b << 18) + (y << 9);
        float4 loc[4];
        float4 run = make_float4(0.f,0.f,0.f,0.f);
        #pragma unroll
        for (int q = 0; q < 4; q++) {
            int i = tid * 4 + q;
            float4 v = make_float4(0.f,0.f,0.f,0.f);
            if (i < Wp) {
                int j = reflW(i - r);
                float g = sgray[k][j];
                float t = stg[k][j];
                v = make_float4(g, t, g*t, g*g);
            }
            run = f4add(run, v);
            loc[q] = run;
        }
        float4 tot = run;
        float4 sc = wscan4(tot, lane);
        float4 excl = f4sub(sc, tot);
        if (lane == 31) wtot[wp] = sc;
        __syncthreads();
        float4 woff = make_float4(0.f,0.f,0.f,0.f);
        #pragma unroll
        for (int w = 0; w < HB_T/32; w++)
            if (w < wp) woff = f4add(woff, wtot[w]);
        float4 off = f4add(excl, woff);
        #pragma unroll
        for (int q = 0; q < 4; q++) {
            int i = tid * 4 + q;
            if (i < Wp) P[i] = f4add(loc[q], off);
        }
        __syncthreads();
        for (int t = tid; t < Wn; t += HB_T) {
            float4 s1 = P[t + 2*r];
            float4 s0 = (t > 0) ? P[t - 1] : make_float4(0.f,0.f,0.f,0.f);
            g_h0[base+t] = s1.x - s0.x;
            g_h1[base+t] = s1.y - s0.y;
            g_h2[base+t] = s1.z - s0.z;
            g_h3[base+t] = s1.w - s0.w;
        }
        // safe to proceed: next iter's P/wtot writes are fenced by its own syncs
    }
}

// ---------------- K2: fused V1(4 fields)+a,b + H2 row scan -----------------
__global__ void __launch_bounds__(VH_T) k_vh(const int* __restrict__ rp)
{
    int r = get_r(rp);
    int Wp = Wn + 2*r;
    float invk2 = 1.0f / (float)((2*r+1)*(2*r+1));
    int bs = blockIdx.x;
    int b   = bs >> 6;
    int seg = bs & (NSEG - 1);
    int y0 = seg * SEG;
    int x = threadIdx.x;
    int base = b << 18;
    int lane = x & 31, wpid = x >> 5;

    __shared__ float sa8[SEG][Wn];
    __shared__ float sb8[SEG][Wn];
    __shared__ float2 P[MAXWP];
    __shared__ float2 wtot[VH_T/32];

    {
        float s0 = 0.f, s1 = 0.f, s2 = 0.f, s3 = 0.f;
        bool interior = (y0 >= r) && (y0 + SEG - 1 + r < Hn);
        if (interior) {
            int o = base + ((y0 - r) << 9) + x;
            for (int d = 0; d <= 2*r; d++) {
                s0 += g_h0[o]; s1 += g_h1[o]; s2 += g_h2[o]; s3 += g_h3[o];
                o += Wn;
            }
            int oa = base + ((y0 + 1 + r) << 9) + x;
            int os = base + ((y0 - r) << 9) + x;
            #pragma unroll
            for (int yy = 0; yy < SEG; yy++) {
                float mI  = s0 * invk2, mp = s1 * invk2;
                float mIp = s2 * invk2, mII = s3 * invk2;
                float a  = (mIp - mI*mp) / (mII - mI*mI + 0.5f);
                sa8[yy][x] = a;
                sb8[yy][x] = mp - a * mI;
                if (yy < SEG - 1) {
                    s0 += g_h0[oa] - g_h0[os];
                    s1 += g_h1[oa] - g_h1[os];
                    s2 += g_h2[oa] - g_h2[os];
                    s3 += g_h3[oa] - g_h3[os];
                    oa += Wn; os += Wn;
                }
            }
        } else {
            for (int d = -r; d <= r; d++) {
                int j = reflH(y0 + d);
                int o = base + (j << 9) + x;
                s0 += g_h0[o]; s1 += g_h1[o]; s2 += g_h2[o]; s3 += g_h3[o];
            }
            #pragma unroll
            for (int yy = 0; yy < SEG; yy++) {
                int y = y0 + yy;
                float mI  = s0 * invk2, mp = s1 * invk2;
                float mIp = s2 * invk2, mII = s3 * invk2;
                float a  = (mIp - mI*mp) / (mII - mI*mI + 0.5f);
                sa8[yy][x] = a;
                sb8[yy][x] = mp - a * mI;
                if (yy < SEG - 1) {
                    int ja = reflH(y + 1 + r);
                    int js = reflH(y - r);
                    int oa = base + (ja << 9) + x;
                    int os = base + (js << 9) + x;
                    s0 += g_h0[oa] - g_h0[os];
                    s1 += g_h1[oa] - g_h1[os];
                    s2 += g_h2[oa] - g_h2[os];
                    s3 += g_h3[oa] - g_h3[os];
                }
            }
        }
    }
    __syncthreads();

    for (int yy = 0; yy < SEG; yy++) {
        int i0 = 2*x, i1 = 2*x + 1;
        float2 v0 = make_float2(0.f,0.f), v1 = make_float2(0.f,0.f);
        if (i0 < Wp) {
            int j = reflW(i0 - r);
            v0 = make_float2(sa8[yy][j], sb8[yy][j]);
        }
        if (i1 < Wp) {
            int j = reflW(i1 - r);
            v1 = make_float2(sa8[yy][j], sb8[yy][j]);
        }
        float2 run = f2add(v0, v1);
        float2 sc = wscan2(run, lane);
        float2 excl = f2sub(sc, run);
        if (lane == 31) wtot[wpid] = sc;
        __syncthreads();
        float2 woff = make_float2(0.f,0.f);
        #pragma unroll
        for (int w = 0; w < VH_T/32; w++)
            if (w < wpid) woff = f2add(woff, wtot[w]);
        float2 off = f2add(excl, woff);
        if (i0 < Wp) P[i0] = f2add(off, v0);
        if (i1 < Wp) P[i1] = f2add(f2add(off, v0), v1);
        __syncthreads();
        int y = y0 + yy;
        float2 s1 = P[x + 2*r];
        float2 s0 = (x > 0) ? P[x - 1] : make_float2(0.f,0.f);
        g_h0[base + (y << 9) + x] = s1.x - s0.x;
        g_h1[base + (y << 9) + x] = s1.y - s0.y;
    }
}

// ---------------- K3: vertical box a,b + t_final (into g_h2) + histogram ---
__global__ void k_vbox_fin(const int* __restrict__ rp,
                           const float* __restrict__ img,
                           const float* __restrict__ atm)
{
    __shared__ unsigned int h3[3*NBINS];        // 48KB: per-channel histograms
    for (int i = threadIdx.x; i < 3*NBINS; i += FIN_T) h3[i] = 0u;
    __syncthreads();

    int r = get_r(rp);
    float invk2 = 1.0f / (float)((2*r+1)*(2*r+1));
    int x   = threadIdx.x;
    int seg = blockIdx.x & (NSEG - 1);
    int b   = blockIdx.x >> 6;
    int base = b << 18;
    int y0 = seg * SEG;
    float A0 = atm[b*3+0], A1 = atm[b*3+1], A2 = atm[b*3+2];
    const float* ib = img + (size_t)b * 3 * HWn;

    float sa = 0.f, sb = 0.f;
    bool interior = (y0 >= r) && (y0 + SEG - 1 + r < Hn);
    int oa, os;
    if (interior) {
        int o = base + ((y0 - r) << 9) + x;
        for (int d = 0; d <= 2*r; d++) { sa += g_h0[o]; sb += g_h1[o]; o += Wn; }
        oa = base + ((y0 + 1 + r) << 9) + x;
        os = base + ((y0 - r) << 9) + x;
    } else {
        for (int d = -r; d <= r; d++) {
            int j = reflH(y0 + d);
            int o = base + (j << 9) + x;
            sa += g_h0[o]; sb += g_h1[o];
        }
        oa = os = 0;
    }
    #pragma unroll
    for (int yy = 0; yy < SEG; yy++) {
        int y = y0 + yy;
        int pix = (y << 9) + x;
        float ma = sa * invk2, mb = sb * invk2;
        float i0 = ib[pix], i1 = ib[HWn + pix], i2 = ib[2*HWn + pix];
        float g = 0.299f*i0 + 0.587f*i1 + 0.114f*i2;
        float tf = fminf(fmaxf(ma * g + mb, 0.1f), 1.0f);
        float inv_t = __fdividef(1.0f, tf + 1e-8f);
        float J0 = fminf(fmaxf((i0 - A0) * inv_t + A0, 0.0f), 1.0f);
        float J1 = fminf(fmaxf((i1 - A1) * inv_t + A1, 0.0f), 1.0f);
        float J2 = fminf(fmaxf((i2 - A2) * inv_t + A2, 0.0f), 1.0f);
        g_h2[base + pix] = tf;     // t_final plane (g_h2 is dead after k_vh)
        atomicAdd(&h3[          min((int)(J0*(float)NBINS), NBINS-1)], 1u);
        atomicAdd(&h3[NBINS   + min((int)(J1*(float)NBINS), NBINS-1)], 1u);
        atomicAdd(&h3[2*NBINS + min((int)(J2*(float)NBINS), NBINS-1)], 1u);
        if (yy < SEG - 1) {
            if (interior) {
                sa += g_h0[oa] - g_h0[os];
                sb += g_h1[oa] - g_h1[os];
                oa += Wn; os += Wn;
            } else {
                int ja = reflH(y + 1 + r);
                int js = reflH(y - r);
                sa += g_h0[base + (ja << 9) + x] - g_h0[base + (js << 9) + x];
                sb += g_h1[base + (ja << 9) + x] - g_h1[base + (js << 9) + x];
            }
        }
    }
    __syncthreads();
    for (int i = threadIdx.x; i < 3*NBINS; i += FIN_T) {
        unsigned int c = h3[i];
        if (c) atomicAdd(&g_hist[b*3*NBINS + i], c);
    }
}

// ---------------- K4: parallel percentile selection ------------------------
#define SEL_T 256
#define CHUNK (NBINS/SEL_T)   // 16 bins per thread
__global__ void __launch_bounds__(SEL_T) k_sel(const float* __restrict__ Ll,
                                               const float* __restrict__ Lh)
{
    int bc = blockIdx.x;
    int b = bc / 3;
    int tid = threadIdx.x;
    int lane = tid & 31, wid = tid >> 5;

    __shared__ unsigned int sh[NBINS];          // 16KB
    __shared__ unsigned int wt[SEL_T/32];
    __shared__ int foundC[2];
    __shared__ unsigned int foundPre[2];

    for (int i = tid; i < NBINS; i += SEL_T)
        sh[i] = g_hist[bc * NBINS + i];
    __syncthreads();

    unsigned int s = 0;
    #pragma unroll
    for (int q = 0; q < CHUNK; q++) s += sh[tid * CHUNK + q];
    unsigned int inc = wscanu(s, lane);
    if (lane == 31) wt[wid] = inc;
    __syncthreads();
    unsigned int woff = 0;
    #pragma unroll
    for (int w = 0; w < SEL_T/32; w++)
        if (w < wid) woff += wt[w];
    unsigned int incl = inc + woff;
    unsigned int excl = incl - s;

    const int n = HWn;
    float tl = (Ll[b] / 100.0f) * (float)n;
    float th = (Lh[b] / 100.0f) * (float)n;
    int li = (int)tl; if (li < 0) li = 0; if (li > n-1) li = n-1;
    int hi = (int)th; if (hi < 0) hi = 0; if (hi > n-1) hi = n-1;
    unsigned int tgt[2] = {(unsigned int)li, (unsigned int)hi};
    #pragma unroll
    for (int t = 0; t < 2; t++) {
        if (excl <= tgt[t] && tgt[t] < incl) {
            foundC[t] = tid;
            foundPre[t] = excl;
        }
    }
    __syncthreads();
    if (tid == 0) {
        #pragma unroll
        for (int t = 0; t < 2; t++) {
            int c0 = foundC[t] * CHUNK;
            unsigned int cum = foundPre[t];
            unsigned int target = tgt[t];
            float pv = 1.0f;
            for (int i = c0; i < c0 + CHUNK; i++) {
                unsigned int c = sh[i];
                if (cum + c > target) {
                    float frac = ((float)(target - cum) + 0.5f) / (float)c;
                    pv = ((float)i + frac) * (1.0f/(float)NBINS);
                    break;
                }
                cum += c;
            }
            g_p[bc*2+t] = pv;
        }
    }
}

// ---------------- K5: final J recompute + stretch (pixel-major float4) -----
__global__ void k_final(const float* __restrict__ img,
                        const float* __restrict__ atm,
                        float* __restrict__ out)
{
    int idx = blockIdx.x * blockDim.x + threadIdx.x;
    if (idx >= NPIX/4) return;
    int b = idx >> 16;                 // HWn/4 = 65536 float4 per batch
    int pix4 = idx & 65535;

    const float4* tf4p = reinterpret_cast<const float4*>(g_h2);
    float4 tf = tf4p[(b << 16) + pix4];
    float it0 = __fdividef(1.0f, tf.x + 1e-8f);
    float it1 = __fdividef(1.0f, tf.y + 1e-8f);
    float it2 = __fdividef(1.0f, tf.z + 1e-8f);
    float it3 = __fdividef(1.0f, tf.w + 1e-8f);

    const float4* img4 = reinterpret_cast<const float4*>(img);
    float4* out4 = reinterpret_cast<float4*>(out);
    #pragma unroll
    for (int c = 0; c < 3; c++) {
        float A  = atm[b*3+c];
        float pl = g_p[(b*3+c)*2+0];
        float ph = g_p[(b*3+c)*2+1];
        float inv = __fdividef(1.0f, ph - pl + 1e-8f);
        int off = ((b*3+c) << 16) + pix4;
        float4 v = img4[off];
        float4 o;
        float J;
        J = fminf(fmaxf((v.x - A) * it0 + A, 0.0f), 1.0f);
        o.x = fminf(fmaxf((fminf(fmaxf(J, pl), ph) - pl) * inv, 0.0f), 1.0f);
        J = fminf(fmaxf((v.y - A) * it1 + A, 0.0f), 1.0f);
        o.y = fminf(fmaxf((fminf(fmaxf(J, pl), ph) - pl) * inv, 0.0f), 1.0f);
        J = fminf(fmaxf((v.z - A) * it2 + A, 0.0f), 1.0f);
        o.z = fminf(fmaxf((fminf(fmaxf(J, pl), ph) - pl) * inv, 0.0f), 1.0f);
        J = fminf(fmaxf((v.w - A) * it3 + A, 0.0f), 1.0f);
        o.w = fminf(fmaxf((fminf(fmaxf(J, pl), ph) - pl) * inv, 0.0f), 1.0f);
        out4[off] = o;
    }
}

// ---------------- launch ----------------------------------------------------
extern "C" void kernel_launch(void* const* d_in, const int* in_sizes, int n_in,
                              void* d_out, int out_size)
{
    const float* img   = (const float*)d_in[0];
    const float* omega = (const float*)d_in[1];
    const float* atm   = (const float*)d_in[2];
    const float* Ll    = (const float*)d_in[3];
    const float* Lh    = (const float*)d_in[4];
    const int*   rp    = (const int*)  d_in[5];
    float* out = (float*)d_out;

    k_hbox4<<<Bn*Hn/HB_ROWS, HB_T>>>(rp, img, omega, atm);
    k_vh<<<Bn*NSEG, VH_T>>>(rp);
    k_vbox_fin<<<Bn*NSEG, FIN_T>>>(rp, img, atm);
    k_sel<<<NBC, SEL_T>>>(Ll, Lh);
    k_final<<<(NPIX/4 + 255)/256, 256>>>(img, atm, out);
}